// round 15
// baseline (speedup 1.0000x reference)
#include <cuda_runtime.h>
#include <cuda_bf16.h>
#include <cstdint>

// ---------------- problem-size constants ----------------
#define NMAX   100000
#define EMAX   1600000
#define HF     128
#define GMAX   64
#define NCHUNK 4

// ---------------- static device scratch (ONLY touched inside kernels) -----
__device__ __nv_bfloat16 g_p16[(size_t)NMAX * HF];   // P1 in bf16
__device__ __nv_bfloat16 g_h16[(size_t)NMAX * HF];   // h1 in bf16
__device__ __nv_bfloat16 g_a2[(size_t)NMAX * HF];    // agg2(h1) in bf16
__device__ int   g_deg[NMAX];
__device__ int   g_rowoff[NMAX + 1];
__device__ int   g_cursor[NMAX];
__device__ int   g_csrc[EMAX];
__device__ int   g_part[512];
__device__ float g_gf[GMAX * HF];

// ---------------- packed helpers -----------------
static __device__ __forceinline__ uint64_t pack2(float x, float y) {
    uint64_t r;
    asm("mov.b64 %0, {%1, %2};" : "=l"(r) : "f"(x), "f"(y));
    return r;
}
static __device__ __forceinline__ void unpack2(uint64_t v, float& x, float& y) {
    asm("mov.b64 {%0, %1}, %2;" : "=f"(x), "=f"(y) : "l"(v));
}
static __device__ __forceinline__ void fma2(uint64_t& d, uint64_t a, uint64_t b) {
    asm("fma.rn.f32x2 %0, %1, %2, %0;" : "+l"(d) : "l"(a), "l"(b));
}
static __device__ __forceinline__ float2 bf2f(uint32_t u) {
    __nv_bfloat162 b = *reinterpret_cast<__nv_bfloat162*>(&u);
    return __bfloat1622float2(b);
}
static __device__ __forceinline__ uint32_t f2bf(float x, float y) {
    __nv_bfloat162 b = __float22bfloat162_rn(make_float2(x, y));
    return *reinterpret_cast<uint32_t*>(&b);
}

// ---------------- CSR build (stream 2) ----------------
__global__ void k_zero(int n) {
    int i = blockIdx.x * blockDim.x + threadIdx.x;
    if (i < n) g_deg[i] = 0;
    if (i < GMAX * HF) g_gf[i] = 0.f;
}

__global__ void k_hist4(const int* __restrict__ dst, int E) {
    int i4 = (blockIdx.x * blockDim.x + threadIdx.x) * 4;
    if (i4 + 4 <= E) {
        int4 d = *(const int4*)&dst[i4];
        atomicAdd(&g_deg[d.x], 1);
        atomicAdd(&g_deg[d.y], 1);
        atomicAdd(&g_deg[d.z], 1);
        atomicAdd(&g_deg[d.w], 1);
    } else {
        for (int i = i4; i < E; i++) atomicAdd(&g_deg[dst[i]], 1);
    }
}

__global__ void k_scan1(int n) {
    __shared__ int s[256];
    int i = blockIdx.x * 256 + threadIdx.x;
    s[threadIdx.x] = (i < n) ? g_deg[i] : 0;
    __syncthreads();
    for (int off = 128; off > 0; off >>= 1) {
        if (threadIdx.x < off) s[threadIdx.x] += s[threadIdx.x + off];
        __syncthreads();
    }
    if (threadIdx.x == 0) g_part[blockIdx.x] = s[0];
}
__global__ void k_scan2(int nb, int n) {
    __shared__ int s[512];
    int t = threadIdx.x;
    int v = (t < nb) ? g_part[t] : 0;
    s[t] = v;
    __syncthreads();
    for (int off = 1; off < 512; off <<= 1) {
        int x = s[t];
        int y = (t >= off) ? s[t - off] : 0;
        __syncthreads();
        s[t] = x + y;
        __syncthreads();
    }
    if (t < nb) g_part[t] = s[t] - v;
    if (t == 511) g_rowoff[n] = s[511];
}
__global__ void k_scan3(int n) {
    __shared__ int s[256];
    int t = threadIdx.x;
    int i = blockIdx.x * 256 + t;
    int v = (i < n) ? g_deg[i] : 0;
    s[t] = v;
    __syncthreads();
    for (int off = 1; off < 256; off <<= 1) {
        int x = s[t];
        int y = (t >= off) ? s[t - off] : 0;
        __syncthreads();
        s[t] = x + y;
        __syncthreads();
    }
    if (i < n) {
        int o = g_part[blockIdx.x] + s[t] - v;
        g_rowoff[i] = o;
        g_cursor[i] = o;
    }
}

__global__ void k_bucket4(const int* __restrict__ src, const int* __restrict__ dst, int E) {
    int i4 = (blockIdx.x * blockDim.x + threadIdx.x) * 4;
    if (i4 + 4 <= E) {
        int4 d = *(const int4*)&dst[i4];
        int4 sv = *(const int4*)&src[i4];
        int p0 = atomicAdd(&g_cursor[d.x], 1);
        int p1 = atomicAdd(&g_cursor[d.y], 1);
        int p2 = atomicAdd(&g_cursor[d.z], 1);
        int p3 = atomicAdd(&g_cursor[d.w], 1);
        g_csrc[p0] = sv.x;
        g_csrc[p1] = sv.y;
        g_csrc[p2] = sv.z;
        g_csrc[p3] = sv.w;
    } else {
        for (int i = i4; i < E; i++) {
            int p = atomicAdd(&g_cursor[dst[i]], 1);
            g_csrc[p] = src[i];
        }
    }
}

// ---------------- GEMM1: g_p16 = bf16(feat @ W1) --------------------------
#define AS_STRIDE 36
__global__ void __launch_bounds__(256) k_gemm(const float* __restrict__ A,
                                              const float* __restrict__ W, int M) {
    __shared__ float As[128 * AS_STRIDE];
    __shared__ float Ws[32 * 128];

    int tid = threadIdx.x;
    int tx = tid & 15;
    int ty = tid >> 4;
    int row0 = blockIdx.x * 128;

    uint64_t acc[8][4];
#pragma unroll
    for (int i = 0; i < 8; i++)
#pragma unroll
        for (int j = 0; j < 4; j++) acc[i][j] = 0ull;

    for (int kt = 0; kt < 4; kt++) {
        int k0 = kt * 32;
#pragma unroll
        for (int j = 0; j < 4; j++) {
            int lin = (j * 256 + tid) * 4;
            int r = lin >> 5;
            int c = lin & 31;
            float4 v = make_float4(0.f, 0.f, 0.f, 0.f);
            if (row0 + r < M)
                v = *(const float4*)&A[(size_t)(row0 + r) * 128 + k0 + c];
            *(float4*)&As[r * AS_STRIDE + c] = v;
        }
#pragma unroll
        for (int j = 0; j < 4; j++) {
            int lin = (j * 256 + tid) * 4;
            int r = lin >> 7;
            int c = lin & 127;
            *(float4*)&Ws[r * 128 + c] = *(const float4*)&W[(size_t)(k0 + r) * 128 + c];
        }
        __syncthreads();

#pragma unroll 8
        for (int kk = 0; kk < 32; kk++) {
            const uint64_t* wrow = (const uint64_t*)&Ws[kk * 128 + tx * 8];
            uint64_t w0 = wrow[0];
            uint64_t w1 = wrow[1];
            uint64_t w2 = wrow[2];
            uint64_t w3 = wrow[3];
#pragma unroll
            for (int i = 0; i < 8; i++) {
                float a = As[(ty * 8 + i) * AS_STRIDE + kk];
                uint64_t ad = pack2(a, a);
                fma2(acc[i][0], ad, w0);
                fma2(acc[i][1], ad, w1);
                fma2(acc[i][2], ad, w2);
                fma2(acc[i][3], ad, w3);
            }
        }
        __syncthreads();
    }

#pragma unroll
    for (int i = 0; i < 8; i++) {
        int r = row0 + ty * 8 + i;
        if (r < M) {
            float v[8];
#pragma unroll
            for (int j = 0; j < 4; j++)
                unpack2(acc[i][j], v[2 * j], v[2 * j + 1]);
            uint4 o;
            o.x = f2bf(v[0], v[1]);
            o.y = f2bf(v[2], v[3]);
            o.z = f2bf(v[4], v[5]);
            o.w = f2bf(v[6], v[7]);
            ((uint4*)(g_p16 + (size_t)r * 128))[tx] = o;
        }
    }
}

// ------- agg1: g_h16 = bf16(relu(agg(g_p16) + b1)), one warp per node -----
__global__ void k_agg(const float* __restrict__ bias, int n) {
    int gt = blockIdx.x * blockDim.x + threadIdx.x;
    int node = gt >> 5;
    if (node >= n) return;
    int lane = threadIdx.x & 31;
    const uint2* __restrict__ in = (const uint2*)g_p16;

    int e   = g_rowoff[node];
    int end = g_rowoff[node + 1];
    float4 acc = make_float4(0.f, 0.f, 0.f, 0.f);

    for (; e + 16 <= end; e += 16) {
        int si[16];
#pragma unroll
        for (int q = 0; q < 16; q++) si[q] = g_csrc[e + q];
        uint2 v[16];
#pragma unroll
        for (int q = 0; q < 16; q++)
            v[q] = __ldg(&in[(size_t)si[q] * 32 + lane]);
#pragma unroll
        for (int q = 0; q < 16; q++) {
            float2 lo = bf2f(v[q].x);
            float2 hi = bf2f(v[q].y);
            acc.x += lo.x; acc.y += lo.y; acc.z += hi.x; acc.w += hi.y;
        }
    }
    for (; e + 4 <= end; e += 4) {
        int s0 = g_csrc[e];
        int s1 = g_csrc[e + 1];
        int s2 = g_csrc[e + 2];
        int s3 = g_csrc[e + 3];
        uint2 v0 = __ldg(&in[(size_t)s0 * 32 + lane]);
        uint2 v1 = __ldg(&in[(size_t)s1 * 32 + lane]);
        uint2 v2 = __ldg(&in[(size_t)s2 * 32 + lane]);
        uint2 v3 = __ldg(&in[(size_t)s3 * 32 + lane]);
        float2 a0 = bf2f(v0.x), b0 = bf2f(v0.y);
        float2 a1 = bf2f(v1.x), b1_ = bf2f(v1.y);
        float2 a2 = bf2f(v2.x), b2_ = bf2f(v2.y);
        float2 a3 = bf2f(v3.x), b3 = bf2f(v3.y);
        acc.x += (a0.x + a1.x) + (a2.x + a3.x);
        acc.y += (a0.y + a1.y) + (a2.y + a3.y);
        acc.z += (b0.x + b1_.x) + (b2_.x + b3.x);
        acc.w += (b0.y + b1_.y) + (b2_.y + b3.y);
    }
    for (; e < end; e++) {
        int s0 = g_csrc[e];
        uint2 v0 = __ldg(&in[(size_t)s0 * 32 + lane]);
        float2 lo = bf2f(v0.x), hi = bf2f(v0.y);
        acc.x += lo.x; acc.y += lo.y; acc.z += hi.x; acc.w += hi.y;
    }
    float4 bb = __ldg(&((const float4*)bias)[lane]);
    acc.x = fmaxf(acc.x + bb.x, 0.f);
    acc.y = fmaxf(acc.y + bb.y, 0.f);
    acc.z = fmaxf(acc.z + bb.z, 0.f);
    acc.w = fmaxf(acc.w + bb.w, 0.f);
    uint2 o;
    o.x = f2bf(acc.x, acc.y);
    o.y = f2bf(acc.z, acc.w);
    ((uint2*)g_h16)[(size_t)node * 32 + lane] = o;
}

// ------- agg2: g_a2[ns:ne] = bf16(agg(g_h16)), one warp per node ----------
__global__ void k_agg2(int ns, int ne) {
    int gt = blockIdx.x * blockDim.x + threadIdx.x;
    int node = ns + (gt >> 5);
    if (node >= ne) return;
    int lane = threadIdx.x & 31;
    const uint2* __restrict__ in = (const uint2*)g_h16;

    int e   = g_rowoff[node];
    int end = g_rowoff[node + 1];
    float4 acc = make_float4(0.f, 0.f, 0.f, 0.f);

    for (; e + 16 <= end; e += 16) {
        int si[16];
#pragma unroll
        for (int q = 0; q < 16; q++) si[q] = g_csrc[e + q];
        uint2 v[16];
#pragma unroll
        for (int q = 0; q < 16; q++)
            v[q] = __ldg(&in[(size_t)si[q] * 32 + lane]);
#pragma unroll
        for (int q = 0; q < 16; q++) {
            float2 lo = bf2f(v[q].x);
            float2 hi = bf2f(v[q].y);
            acc.x += lo.x; acc.y += lo.y; acc.z += hi.x; acc.w += hi.y;
        }
    }
    for (; e + 4 <= end; e += 4) {
        int s0 = g_csrc[e];
        int s1 = g_csrc[e + 1];
        int s2 = g_csrc[e + 2];
        int s3 = g_csrc[e + 3];
        uint2 v0 = __ldg(&in[(size_t)s0 * 32 + lane]);
        uint2 v1 = __ldg(&in[(size_t)s1 * 32 + lane]);
        uint2 v2 = __ldg(&in[(size_t)s2 * 32 + lane]);
        uint2 v3 = __ldg(&in[(size_t)s3 * 32 + lane]);
        float2 a0 = bf2f(v0.x), b0 = bf2f(v0.y);
        float2 a1 = bf2f(v1.x), b1_ = bf2f(v1.y);
        float2 a2 = bf2f(v2.x), b2_ = bf2f(v2.y);
        float2 a3 = bf2f(v3.x), b3 = bf2f(v3.y);
        acc.x += (a0.x + a1.x) + (a2.x + a3.x);
        acc.y += (a0.y + a1.y) + (a2.y + a3.y);
        acc.z += (b0.x + b1_.x) + (b2_.x + b3.x);
        acc.w += (b0.y + b1_.y) + (b2_.y + b3.y);
    }
    for (; e < end; e++) {
        int s0 = g_csrc[e];
        uint2 v0 = __ldg(&in[(size_t)s0 * 32 + lane]);
        float2 lo = bf2f(v0.x), hi = bf2f(v0.y);
        acc.x += lo.x; acc.y += lo.y; acc.z += hi.x; acc.w += hi.y;
    }
    uint2 o;
    o.x = f2bf(acc.x, acc.y);
    o.y = f2bf(acc.z, acc.w);
    ((uint2*)g_a2)[(size_t)node * 32 + lane] = o;
}

// ------- GEMM2 + pool: g_gf += colsums(relu(g_a2[rows] @ W2 + b2)) --------
// A read as bf16, fp32 smem tile; f32x2 mainloop; h2 written bf16 into
// overlaid smem (As/Ws dead), pooled per-feature with ~1-2 atomics each.
#define H_STRIDE 136   // bf16 row stride (272B, 16B-aligned)
__global__ void __launch_bounds__(256) k_gemm2(const float* __restrict__ W,
                                               const float* __restrict__ bias,
                                               const int* __restrict__ gid,
                                               int rowStart, int N) {
    __shared__ char sm[128 * AS_STRIDE * 4 + 32 * 128 * 4 + 512];  // 35328
    float* As = (float*)sm;                                // [128][36]
    float* Ws = (float*)(sm + 128 * AS_STRIDE * 4);        // [32][128]
    __nv_bfloat16* H = (__nv_bfloat16*)sm;                 // overlay, [128][136]
    int* gids = (int*)(sm + 128 * AS_STRIDE * 4 + 32 * 128 * 4);

    int tid = threadIdx.x;
    int tx = tid & 15;
    int ty = tid >> 4;
    int row0 = rowStart + blockIdx.x * 128;

    if (tid < 128) {
        int node = row0 + tid;
        gids[tid] = (node < N) ? __ldg(&gid[node]) : -1;
    }

    uint64_t acc[8][4];
#pragma unroll
    for (int i = 0; i < 8; i++)
#pragma unroll
        for (int j = 0; j < 4; j++) acc[i][j] = 0ull;

    for (int kt = 0; kt < 4; kt++) {
        int k0 = kt * 32;
#pragma unroll
        for (int j = 0; j < 4; j++) {
            int lin = (j * 256 + tid) * 4;
            int r = lin >> 5;
            int c = lin & 31;
            float4 v = make_float4(0.f, 0.f, 0.f, 0.f);
            if (row0 + r < N) {
                uint2 u = *(const uint2*)&g_a2[(size_t)(row0 + r) * 128 + k0 + c];
                float2 lo = bf2f(u.x), hi = bf2f(u.y);
                v = make_float4(lo.x, lo.y, hi.x, hi.y);
            }
            *(float4*)&As[r * AS_STRIDE + c] = v;
        }
#pragma unroll
        for (int j = 0; j < 4; j++) {
            int lin = (j * 256 + tid) * 4;
            int r = lin >> 7;
            int c = lin & 127;
            *(float4*)&Ws[r * 128 + c] = *(const float4*)&W[(size_t)(k0 + r) * 128 + c];
        }
        __syncthreads();

#pragma unroll 8
        for (int kk = 0; kk < 32; kk++) {
            const uint64_t* wrow = (const uint64_t*)&Ws[kk * 128 + tx * 8];
            uint64_t w0 = wrow[0];
            uint64_t w1 = wrow[1];
            uint64_t w2 = wrow[2];
            uint64_t w3 = wrow[3];
#pragma unroll
            for (int i = 0; i < 8; i++) {
                float a = As[(ty * 8 + i) * AS_STRIDE + kk];
                uint64_t ad = pack2(a, a);
                fma2(acc[i][0], ad, w0);
                fma2(acc[i][1], ad, w1);
                fma2(acc[i][2], ad, w2);
                fma2(acc[i][3], ad, w3);
            }
        }
        __syncthreads();
    }

    // ---- epilogue: bias+ReLU, bf16 h2 into overlaid smem ----
    float bb[8];
#pragma unroll
    for (int j = 0; j < 8; j++) bb[j] = __ldg(&bias[tx * 8 + j]);

#pragma unroll
    for (int i = 0; i < 8; i++) {
        int lr = ty * 8 + i;
        float v[8];
#pragma unroll
        for (int j = 0; j < 4; j++)
            unpack2(acc[i][j], v[2 * j], v[2 * j + 1]);
        uint4 o;
        o.x = f2bf(fmaxf(v[0] + bb[0], 0.f), fmaxf(v[1] + bb[1], 0.f));
        o.y = f2bf(fmaxf(v[2] + bb[2], 0.f), fmaxf(v[3] + bb[3], 0.f));
        o.z = f2bf(fmaxf(v[4] + bb[4], 0.f), fmaxf(v[5] + bb[5], 0.f));
        o.w = f2bf(fmaxf(v[6] + bb[6], 0.f), fmaxf(v[7] + bb[7], 0.f));
        *(uint4*)&H[lr * H_STRIDE + tx * 8] = o;
    }
    __syncthreads();

    // ---- pool: one feature per thread, serial over sorted rows ----
    if (tid < 128) {
        int f = tid;
        float run = 0.f;
        int curg = gids[0];
        for (int r = 0; r < 128; r++) {
            int gg = gids[r];
            if (gg < 0) break;
            if (gg != curg) {
                atomicAdd(&g_gf[curg * 128 + f], run);
                run = 0.f;
                curg = gg;
            }
            run += __bfloat162float(H[r * H_STRIDE + f]);
        }
        if (curg >= 0) atomicAdd(&g_gf[curg * 128 + f], run);
    }
}

// ------- final projection ------------------
__global__ void k_final(const float* __restrict__ Wp, const float* __restrict__ bp,
                        float* __restrict__ out, const int* __restrict__ gid,
                        int n, int G, int C) {
    int tid = blockIdx.x * blockDim.x + threadIdx.x;
    if (tid >= G * C) return;
    int g = tid / C;
    int c = tid % C;
    int lo = 0, hi = n;
    while (lo < hi) { int mid = (lo + hi) >> 1; if (gid[mid] < g) lo = mid + 1; else hi = mid; }
    int beg = lo;
    lo = 0; hi = n;
    while (lo < hi) { int mid = (lo + hi) >> 1; if (gid[mid] < g + 1) lo = mid + 1; else hi = mid; }
    int cnt = lo - beg;
    float inv = 1.f / ((cnt > 0) ? (float)cnt : 1.f);
    float acc = 0.f;
#pragma unroll 8
    for (int k = 0; k < 128; k++)
        acc += (g_gf[g * 128 + k] * inv) * Wp[k * C + c];
    out[tid] = acc + bp[c];
}

// ---------------- launch --------------------------------------------------
extern "C" void kernel_launch(void* const* d_in, const int* in_sizes, int n_in,
                              void* d_out, int out_size) {
    const float* feat = (const float*)d_in[0];
    const float* W1   = (const float*)d_in[1];
    const float* b1   = (const float*)d_in[2];
    const float* W2   = (const float*)d_in[3];
    const float* b2   = (const float*)d_in[4];
    const float* Wp   = (const float*)d_in[5];
    const float* bp   = (const float*)d_in[6];
    const int*   src  = (const int*)d_in[7];
    const int*   dst  = (const int*)d_in[8];
    const int*   gid  = (const int*)d_in[9];

    int N = in_sizes[0] / HF;
    int E = in_sizes[7];
    int C = in_sizes[6];
    int G = out_size / C;

    static cudaStream_t s2 = nullptr;
    static cudaEvent_t evFork = nullptr, evCsr = nullptr, evG2 = nullptr;
    static cudaEvent_t evA[NCHUNK];
    if (!s2) {
        cudaStreamCreateWithFlags(&s2, cudaStreamNonBlocking);
        cudaEventCreateWithFlags(&evFork, cudaEventDisableTiming);
        cudaEventCreateWithFlags(&evCsr, cudaEventDisableTiming);
        cudaEventCreateWithFlags(&evG2, cudaEventDisableTiming);
        for (int i = 0; i < NCHUNK; i++)
            cudaEventCreateWithFlags(&evA[i], cudaEventDisableTiming);
    }

    int scanBlocks = (N + 255) / 256;

    // ---- fork: CSR build on s2, GEMM1 on main ----
    cudaEventRecord(evFork, 0);
    cudaStreamWaitEvent(s2, evFork, 0);

    k_zero   <<<(N + 255) / 256, 256, 0, s2>>>(N);
    k_hist4  <<<(E / 4 + 255) / 256, 256, 0, s2>>>(dst, E);
    k_scan1  <<<scanBlocks, 256, 0, s2>>>(N);
    k_scan2  <<<1, 512, 0, s2>>>(scanBlocks, N);
    k_scan3  <<<scanBlocks, 256, 0, s2>>>(N);
    k_bucket4<<<(E / 4 + 255) / 256, 256, 0, s2>>>(src, dst, E);
    cudaEventRecord(evCsr, s2);

    // GEMM1: P1 = bf16(feat @ W1) -> g_p16 (no CSR dependency)
    k_gemm<<<(N + 127) / 128, 256>>>(feat, W1, N);

    cudaStreamWaitEvent(0, evCsr, 0);

    // h1 = bf16(relu(agg(P1) + b1)): g_p16 -> g_h16
    k_agg<<<(N * 32 + 255) / 256, 256>>>(b1, N);

    // ---- layer 2 pipelined: agg2 chunk (stream 0) -> GEMM2+pool chunk (s2) --
    int chunkN = (((N + NCHUNK - 1) / NCHUNK) + 127) & ~127;   // 128-aligned
    for (int ci = 0; ci < NCHUNK; ci++) {
        int ns = ci * chunkN;
        int ne = ns + chunkN; if (ne > N) ne = N;
        if (ns >= ne) continue;
        int cN = ne - ns;
        k_agg2<<<(cN * 32 + 255) / 256, 256>>>(ns, ne);
        cudaEventRecord(evA[ci], 0);
        cudaStreamWaitEvent(s2, evA[ci], 0);
        k_gemm2<<<(cN + 127) / 128, 256, 0, s2>>>(W2, b2, gid, ns, N);
    }
    cudaEventRecord(evG2, s2);
    cudaStreamWaitEvent(0, evG2, 0);

    // final projection (reads g_gf)
    k_final<<<(G * C + 255) / 256, 256>>>(Wp, bp, (float*)d_out, gid, N, G, C);
}

// round 16
// speedup vs baseline: 1.8392x; 1.8392x over previous
#include <cuda_runtime.h>
#include <cuda_bf16.h>
#include <cstdint>

// ---------------- problem-size constants ----------------
#define NMAX   100000
#define EMAX   1600000
#define HF     128
#define GMAX   64

// ---------------- static device scratch (ONLY touched inside kernels) -----
__device__ __nv_bfloat16 g_p16[(size_t)NMAX * HF];   // P1 in bf16
__device__ __nv_bfloat16 g_h16[(size_t)NMAX * HF];   // h1 in bf16
__device__ int   g_deg[NMAX];
__device__ int   g_rowoff[NMAX + 1];
__device__ int   g_cursor[NMAX];
__device__ int   g_csrc[EMAX];
__device__ int   g_part[512];
__device__ float g_gf[GMAX * HF];

// ---------------- packed helpers -----------------
static __device__ __forceinline__ uint64_t pack2(float x, float y) {
    uint64_t r;
    asm("mov.b64 %0, {%1, %2};" : "=l"(r) : "f"(x), "f"(y));
    return r;
}
static __device__ __forceinline__ void unpack2(uint64_t v, float& x, float& y) {
    asm("mov.b64 {%0, %1}, %2;" : "=f"(x), "=f"(y) : "l"(v));
}
static __device__ __forceinline__ void fma2(uint64_t& d, uint64_t a, uint64_t b) {
    asm("fma.rn.f32x2 %0, %1, %2, %0;" : "+l"(d) : "l"(a), "l"(b));
}
// bf16x2 word -> packed f32x2 (exact: bf16 is the top 16 bits of fp32)
static __device__ __forceinline__ uint64_t bfpair(uint32_t u) {
    uint32_t lo = u << 16;
    uint32_t hi = u & 0xFFFF0000u;
    uint64_t r;
    asm("mov.b64 %0, {%1, %2};" : "=l"(r) : "r"(lo), "r"(hi));
    return r;
}
static __device__ __forceinline__ void add2(uint64_t& d, uint64_t a) {
    asm("add.rn.f32x2 %0, %0, %1;" : "+l"(d) : "l"(a));
}
static __device__ __forceinline__ float2 bf2f(uint32_t u) {
    __nv_bfloat162 b = *reinterpret_cast<__nv_bfloat162*>(&u);
    return __bfloat1622float2(b);
}
static __device__ __forceinline__ uint32_t f2bf(float x, float y) {
    __nv_bfloat162 b = __float22bfloat162_rn(make_float2(x, y));
    return *reinterpret_cast<uint32_t*>(&b);
}

// ---------------- CSR build (stream 2) ----------------
__global__ void k_zero(int n) {
    int i = blockIdx.x * blockDim.x + threadIdx.x;
    if (i < n) g_deg[i] = 0;
    if (i < GMAX * HF) g_gf[i] = 0.f;
}

__global__ void k_hist4(const int* __restrict__ dst, int E) {
    int i4 = (blockIdx.x * blockDim.x + threadIdx.x) * 4;
    if (i4 + 4 <= E) {
        int4 d = *(const int4*)&dst[i4];
        atomicAdd(&g_deg[d.x], 1);
        atomicAdd(&g_deg[d.y], 1);
        atomicAdd(&g_deg[d.z], 1);
        atomicAdd(&g_deg[d.w], 1);
    } else {
        for (int i = i4; i < E; i++) atomicAdd(&g_deg[dst[i]], 1);
    }
}

__global__ void k_scan1(int n) {
    __shared__ int s[256];
    int i = blockIdx.x * 256 + threadIdx.x;
    s[threadIdx.x] = (i < n) ? g_deg[i] : 0;
    __syncthreads();
    for (int off = 128; off > 0; off >>= 1) {
        if (threadIdx.x < off) s[threadIdx.x] += s[threadIdx.x + off];
        __syncthreads();
    }
    if (threadIdx.x == 0) g_part[blockIdx.x] = s[0];
}
__global__ void k_scan2(int nb, int n) {
    __shared__ int s[512];
    int t = threadIdx.x;
    int v = (t < nb) ? g_part[t] : 0;
    s[t] = v;
    __syncthreads();
    for (int off = 1; off < 512; off <<= 1) {
        int x = s[t];
        int y = (t >= off) ? s[t - off] : 0;
        __syncthreads();
        s[t] = x + y;
        __syncthreads();
    }
    if (t < nb) g_part[t] = s[t] - v;
    if (t == 511) g_rowoff[n] = s[511];
}
__global__ void k_scan3(int n) {
    __shared__ int s[256];
    int t = threadIdx.x;
    int i = blockIdx.x * 256 + t;
    int v = (i < n) ? g_deg[i] : 0;
    s[t] = v;
    __syncthreads();
    for (int off = 1; off < 256; off <<= 1) {
        int x = s[t];
        int y = (t >= off) ? s[t - off] : 0;
        __syncthreads();
        s[t] = x + y;
        __syncthreads();
    }
    if (i < n) {
        int o = g_part[blockIdx.x] + s[t] - v;
        g_rowoff[i] = o;
        g_cursor[i] = o;
    }
}

__global__ void k_bucket4(const int* __restrict__ src, const int* __restrict__ dst, int E) {
    int i4 = (blockIdx.x * blockDim.x + threadIdx.x) * 4;
    if (i4 + 4 <= E) {
        int4 d = *(const int4*)&dst[i4];
        int4 sv = *(const int4*)&src[i4];
        int p0 = atomicAdd(&g_cursor[d.x], 1);
        int p1 = atomicAdd(&g_cursor[d.y], 1);
        int p2 = atomicAdd(&g_cursor[d.z], 1);
        int p3 = atomicAdd(&g_cursor[d.w], 1);
        g_csrc[p0] = sv.x;
        g_csrc[p1] = sv.y;
        g_csrc[p2] = sv.z;
        g_csrc[p3] = sv.w;
    } else {
        for (int i = i4; i < E; i++) {
            int p = atomicAdd(&g_cursor[dst[i]], 1);
            g_csrc[p] = src[i];
        }
    }
}

// ---------------- GEMM1: g_p16 = bf16(feat @ W1) --------------------------
#define AS_STRIDE 36
__global__ void __launch_bounds__(256) k_gemm(const float* __restrict__ A,
                                              const float* __restrict__ W, int M) {
    __shared__ float As[128 * AS_STRIDE];
    __shared__ float Ws[32 * 128];

    int tid = threadIdx.x;
    int tx = tid & 15;
    int ty = tid >> 4;
    int row0 = blockIdx.x * 128;

    uint64_t acc[8][4];
#pragma unroll
    for (int i = 0; i < 8; i++)
#pragma unroll
        for (int j = 0; j < 4; j++) acc[i][j] = 0ull;

    for (int kt = 0; kt < 4; kt++) {
        int k0 = kt * 32;
#pragma unroll
        for (int j = 0; j < 4; j++) {
            int lin = (j * 256 + tid) * 4;
            int r = lin >> 5;
            int c = lin & 31;
            float4 v = make_float4(0.f, 0.f, 0.f, 0.f);
            if (row0 + r < M)
                v = *(const float4*)&A[(size_t)(row0 + r) * 128 + k0 + c];
            *(float4*)&As[r * AS_STRIDE + c] = v;
        }
#pragma unroll
        for (int j = 0; j < 4; j++) {
            int lin = (j * 256 + tid) * 4;
            int r = lin >> 7;
            int c = lin & 127;
            *(float4*)&Ws[r * 128 + c] = *(const float4*)&W[(size_t)(k0 + r) * 128 + c];
        }
        __syncthreads();

#pragma unroll 8
        for (int kk = 0; kk < 32; kk++) {
            const uint64_t* wrow = (const uint64_t*)&Ws[kk * 128 + tx * 8];
            uint64_t w0 = wrow[0];
            uint64_t w1 = wrow[1];
            uint64_t w2 = wrow[2];
            uint64_t w3 = wrow[3];
#pragma unroll
            for (int i = 0; i < 8; i++) {
                float a = As[(ty * 8 + i) * AS_STRIDE + kk];
                uint64_t ad = pack2(a, a);
                fma2(acc[i][0], ad, w0);
                fma2(acc[i][1], ad, w1);
                fma2(acc[i][2], ad, w2);
                fma2(acc[i][3], ad, w3);
            }
        }
        __syncthreads();
    }

#pragma unroll
    for (int i = 0; i < 8; i++) {
        int r = row0 + ty * 8 + i;
        if (r < M) {
            float v[8];
#pragma unroll
            for (int j = 0; j < 4; j++)
                unpack2(acc[i][j], v[2 * j], v[2 * j + 1]);
            uint4 o;
            o.x = f2bf(v[0], v[1]);
            o.y = f2bf(v[2], v[3]);
            o.z = f2bf(v[4], v[5]);
            o.w = f2bf(v[6], v[7]);
            ((uint4*)(g_p16 + (size_t)r * 128))[tx] = o;
        }
    }
}

// ------- agg1: g_h16 = bf16(relu(agg(g_p16) + b1)), one warp per node -----
// Packed accumulate: bf16x2 -> f32x2 via bit-shift (exact), add.rn.f32x2.
__global__ void k_agg(const float* __restrict__ bias, int n) {
    int gt = blockIdx.x * blockDim.x + threadIdx.x;
    int node = gt >> 5;
    if (node >= n) return;
    int lane = threadIdx.x & 31;
    const uint2* __restrict__ in = (const uint2*)g_p16;

    int e   = g_rowoff[node];
    int end = g_rowoff[node + 1];
    uint64_t acc01 = pack2(0.f, 0.f);
    uint64_t acc23 = pack2(0.f, 0.f);

    for (; e + 16 <= end; e += 16) {
        int si[16];
#pragma unroll
        for (int q = 0; q < 16; q++) si[q] = g_csrc[e + q];
        uint2 v[16];
#pragma unroll
        for (int q = 0; q < 16; q++)
            v[q] = __ldg(&in[(size_t)si[q] * 32 + lane]);
#pragma unroll
        for (int q = 0; q < 16; q++) {
            add2(acc01, bfpair(v[q].x));
            add2(acc23, bfpair(v[q].y));
        }
    }
    for (; e + 4 <= end; e += 4) {
        int s0 = g_csrc[e];
        int s1 = g_csrc[e + 1];
        int s2 = g_csrc[e + 2];
        int s3 = g_csrc[e + 3];
        uint2 v0 = __ldg(&in[(size_t)s0 * 32 + lane]);
        uint2 v1 = __ldg(&in[(size_t)s1 * 32 + lane]);
        uint2 v2 = __ldg(&in[(size_t)s2 * 32 + lane]);
        uint2 v3 = __ldg(&in[(size_t)s3 * 32 + lane]);
        add2(acc01, bfpair(v0.x)); add2(acc23, bfpair(v0.y));
        add2(acc01, bfpair(v1.x)); add2(acc23, bfpair(v1.y));
        add2(acc01, bfpair(v2.x)); add2(acc23, bfpair(v2.y));
        add2(acc01, bfpair(v3.x)); add2(acc23, bfpair(v3.y));
    }
    for (; e < end; e++) {
        int s0 = g_csrc[e];
        uint2 v0 = __ldg(&in[(size_t)s0 * 32 + lane]);
        add2(acc01, bfpair(v0.x));
        add2(acc23, bfpair(v0.y));
    }
    float4 acc;
    unpack2(acc01, acc.x, acc.y);
    unpack2(acc23, acc.z, acc.w);
    float4 bb = __ldg(&((const float4*)bias)[lane]);
    acc.x = fmaxf(acc.x + bb.x, 0.f);
    acc.y = fmaxf(acc.y + bb.y, 0.f);
    acc.z = fmaxf(acc.z + bb.z, 0.f);
    acc.w = fmaxf(acc.w + bb.w, 0.f);
    uint2 o;
    o.x = f2bf(acc.x, acc.y);
    o.y = f2bf(acc.z, acc.w);
    ((uint2*)g_h16)[(size_t)node * 32 + lane] = o;
}

// ------- fused layer 2 + pooling: g_gf += colsums(relu(agg(g_h16)@W2+b2)) -
#define FA_STRIDE 132
#define SM_FUSED  (128 * FA_STRIDE * 4 + 32 * 128 * 4)   // 83968 bytes
__global__ void __launch_bounds__(256) k_fused(const float* __restrict__ W,
                                               const float* __restrict__ bias,
                                               const int* __restrict__ gid, int N) {
    extern __shared__ float smem[];
    float* As = smem;                      // [128][FA_STRIDE]
    float* Ws = smem + 128 * FA_STRIDE;    // [32][128]

    int tid = threadIdx.x;
    int wid = tid >> 5;
    int lane = tid & 31;
    int row0 = blockIdx.x * 128;
    const uint2* __restrict__ in = (const uint2*)g_h16;

    // ---- Phase A: gather 16 nodes per warp into smem, packed accumulate ----
    for (int j = 0; j < 16; j++) {
        int lr = wid * 16 + j;
        int node = row0 + lr;
        uint64_t acc01 = pack2(0.f, 0.f);
        uint64_t acc23 = pack2(0.f, 0.f);
        if (node < N) {
            int e   = g_rowoff[node];
            int end = g_rowoff[node + 1];
            for (; e + 16 <= end; e += 16) {
                int si[16];
#pragma unroll
                for (int q = 0; q < 16; q++) si[q] = g_csrc[e + q];
                uint2 v[16];
#pragma unroll
                for (int q = 0; q < 16; q++)
                    v[q] = __ldg(&in[(size_t)si[q] * 32 + lane]);
#pragma unroll
                for (int q = 0; q < 16; q++) {
                    add2(acc01, bfpair(v[q].x));
                    add2(acc23, bfpair(v[q].y));
                }
            }
            for (; e + 4 <= end; e += 4) {
                int s0 = g_csrc[e];
                int s1 = g_csrc[e + 1];
                int s2 = g_csrc[e + 2];
                int s3 = g_csrc[e + 3];
                uint2 v0 = __ldg(&in[(size_t)s0 * 32 + lane]);
                uint2 v1 = __ldg(&in[(size_t)s1 * 32 + lane]);
                uint2 v2 = __ldg(&in[(size_t)s2 * 32 + lane]);
                uint2 v3 = __ldg(&in[(size_t)s3 * 32 + lane]);
                add2(acc01, bfpair(v0.x)); add2(acc23, bfpair(v0.y));
                add2(acc01, bfpair(v1.x)); add2(acc23, bfpair(v1.y));
                add2(acc01, bfpair(v2.x)); add2(acc23, bfpair(v2.y));
                add2(acc01, bfpair(v3.x)); add2(acc23, bfpair(v3.y));
            }
            for (; e < end; e++) {
                int s0 = g_csrc[e];
                uint2 v0 = __ldg(&in[(size_t)s0 * 32 + lane]);
                add2(acc01, bfpair(v0.x));
                add2(acc23, bfpair(v0.y));
            }
        }
        float4 acc;
        unpack2(acc01, acc.x, acc.y);
        unpack2(acc23, acc.z, acc.w);
        *(float4*)&As[lr * FA_STRIDE + lane * 4] = acc;
    }
    __syncthreads();

    // ---- Phase B: GEMM from smem As, W tiles ----
    int tx = tid & 15;
    int ty = tid >> 4;

    uint64_t acc[8][4];
#pragma unroll
    for (int i = 0; i < 8; i++)
#pragma unroll
        for (int j = 0; j < 4; j++) acc[i][j] = 0ull;

    for (int kt = 0; kt < 4; kt++) {
        int k0 = kt * 32;
#pragma unroll
        for (int j = 0; j < 4; j++) {
            int lin = (j * 256 + tid) * 4;
            int r = lin >> 7;
            int c = lin & 127;
            *(float4*)&Ws[r * 128 + c] = *(const float4*)&W[(size_t)(k0 + r) * 128 + c];
        }
        __syncthreads();

#pragma unroll 8
        for (int kk = 0; kk < 32; kk++) {
            const uint64_t* wrow = (const uint64_t*)&Ws[kk * 128 + tx * 8];
            uint64_t w0 = wrow[0];
            uint64_t w1 = wrow[1];
            uint64_t w2 = wrow[2];
            uint64_t w3 = wrow[3];
#pragma unroll
            for (int i = 0; i < 8; i++) {
                float a = As[(ty * 8 + i) * FA_STRIDE + k0 + kk];
                uint64_t ad = pack2(a, a);
                fma2(acc[i][0], ad, w0);
                fma2(acc[i][1], ad, w1);
                fma2(acc[i][2], ad, w2);
                fma2(acc[i][3], ad, w3);
            }
        }
        __syncthreads();
    }

    // ---- Epilogue: bias+ReLU into smem (As is dead) ----
    float bb[8];
#pragma unroll
    for (int j = 0; j < 8; j++) bb[j] = __ldg(&bias[tx * 8 + j]);

#pragma unroll
    for (int i = 0; i < 8; i++) {
        int lr = ty * 8 + i;
        float v[8];
#pragma unroll
        for (int j = 0; j < 4; j++)
            unpack2(acc[i][j], v[2 * j], v[2 * j + 1]);
        float4 o0, o1;
        o0.x = fmaxf(v[0] + bb[0], 0.f);
        o0.y = fmaxf(v[1] + bb[1], 0.f);
        o0.z = fmaxf(v[2] + bb[2], 0.f);
        o0.w = fmaxf(v[3] + bb[3], 0.f);
        o1.x = fmaxf(v[4] + bb[4], 0.f);
        o1.y = fmaxf(v[5] + bb[5], 0.f);
        o1.z = fmaxf(v[6] + bb[6], 0.f);
        o1.w = fmaxf(v[7] + bb[7], 0.f);
        *(float4*)&As[lr * FA_STRIDE + tx * 8]     = o0;
        *(float4*)&As[lr * FA_STRIDE + tx * 8 + 4] = o1;
    }

    // gid window into smem (reuse Ws)
    int* gids = (int*)Ws;
    if (tid < 128) {
        int node = row0 + tid;
        gids[tid] = (node < N) ? __ldg(&gid[node]) : -1;
    }
    __syncthreads();

    // ---- Pool: one feature per thread, serial over sorted rows ----
    if (tid < 128) {
        int f = tid;
        float run = 0.f;
        int curg = gids[0];
        for (int r = 0; r < 128; r++) {
            int gg = gids[r];
            if (gg < 0) break;
            if (gg != curg) {
                atomicAdd(&g_gf[curg * 128 + f], run);
                run = 0.f;
                curg = gg;
            }
            run += As[r * FA_STRIDE + f];
        }
        if (curg >= 0) atomicAdd(&g_gf[curg * 128 + f], run);
    }
}

// ------- final projection ------------------
__global__ void k_final(const float* __restrict__ Wp, const float* __restrict__ bp,
                        float* __restrict__ out, const int* __restrict__ gid,
                        int n, int G, int C) {
    int tid = blockIdx.x * blockDim.x + threadIdx.x;
    if (tid >= G * C) return;
    int g = tid / C;
    int c = tid % C;
    int lo = 0, hi = n;
    while (lo < hi) { int mid = (lo + hi) >> 1; if (gid[mid] < g) lo = mid + 1; else hi = mid; }
    int beg = lo;
    lo = 0; hi = n;
    while (lo < hi) { int mid = (lo + hi) >> 1; if (gid[mid] < g + 1) lo = mid + 1; else hi = mid; }
    int cnt = lo - beg;
    float inv = 1.f / ((cnt > 0) ? (float)cnt : 1.f);
    float acc = 0.f;
#pragma unroll 8
    for (int k = 0; k < 128; k++)
        acc += (g_gf[g * 128 + k] * inv) * Wp[k * C + c];
    out[tid] = acc + bp[c];
}

// ---------------- launch --------------------------------------------------
extern "C" void kernel_launch(void* const* d_in, const int* in_sizes, int n_in,
                              void* d_out, int out_size) {
    const float* feat = (const float*)d_in[0];
    const float* W1   = (const float*)d_in[1];
    const float* b1   = (const float*)d_in[2];
    const float* W2   = (const float*)d_in[3];
    const float* b2   = (const float*)d_in[4];
    const float* Wp   = (const float*)d_in[5];
    const float* bp   = (const float*)d_in[6];
    const int*   src  = (const int*)d_in[7];
    const int*   dst  = (const int*)d_in[8];
    const int*   gid  = (const int*)d_in[9];

    int N = in_sizes[0] / HF;
    int E = in_sizes[7];
    int C = in_sizes[6];
    int G = out_size / C;

    static cudaStream_t s2 = nullptr;
    static cudaEvent_t evFork = nullptr, evCsr = nullptr;
    if (!s2) {
        cudaStreamCreateWithFlags(&s2, cudaStreamNonBlocking);
        cudaEventCreateWithFlags(&evFork, cudaEventDisableTiming);
        cudaEventCreateWithFlags(&evCsr, cudaEventDisableTiming);
        cudaFuncSetAttribute(k_fused, cudaFuncAttributeMaxDynamicSharedMemorySize, SM_FUSED);
    }

    int scanBlocks = (N + 255) / 256;

    // ---- fork: CSR build on s2, GEMM1 on main (single fork/join, proven) ----
    cudaEventRecord(evFork, 0);
    cudaStreamWaitEvent(s2, evFork, 0);

    k_zero   <<<(N + 255) / 256, 256, 0, s2>>>(N);
    k_hist4  <<<(E / 4 + 255) / 256, 256, 0, s2>>>(dst, E);
    k_scan1  <<<scanBlocks, 256, 0, s2>>>(N);
    k_scan2  <<<1, 512, 0, s2>>>(scanBlocks, N);
    k_scan3  <<<scanBlocks, 256, 0, s2>>>(N);
    k_bucket4<<<(E / 4 + 255) / 256, 256, 0, s2>>>(src, dst, E);
    cudaEventRecord(evCsr, s2);

    // GEMM1: P1 = bf16(feat @ W1) -> g_p16 (no CSR dependency)
    k_gemm<<<(N + 127) / 128, 256>>>(feat, W1, N);

    cudaStreamWaitEvent(0, evCsr, 0);

    // h1 = bf16(relu(agg(P1) + b1)): g_p16 -> g_h16
    k_agg<<<(N * 32 + 255) / 256, 256>>>(b1, N);

    // fused layer 2 + pooling: g_h16 -> g_gf (h2 never leaves smem)
    k_fused<<<(N + 127) / 128, 256, SM_FUSED>>>(W2, b2, gid, N);

    // final projection
    k_final<<<(G * C + 255) / 256, 256>>>(Wp, bp, (float*)d_out, gid, N, G, C);
}